// round 3
// baseline (speedup 1.0000x reference)
#include <cuda_runtime.h>

#define BB 64
#define TT 512
#define HH 768
#define LL 9
#define LOG2E 1.4426950408889634f
#define LN2   0.6931471805599453f

__device__ __align__(16) float g_logits[BB * TT * LL];
__device__ float g_ll[BB];

__device__ __forceinline__ float ex2f_(float x) {
    float y; asm("ex2.approx.ftz.f32 %0, %1;" : "=f"(y) : "f"(x)); return y;
}
__device__ __forceinline__ float lg2f_(float x) {
    float y; asm("lg2.approx.ftz.f32 %0, %1;" : "=f"(y) : "f"(x)); return y;
}
__device__ __forceinline__ int wredi(int v) {
    #pragma unroll
    for (int o = 16; o; o >>= 1) v += __shfl_xor_sync(0xffffffffu, v, o);
    return v;
}
__device__ __forceinline__ float wredf(float v) {
    #pragma unroll
    for (int o = 16; o; o >>= 1) v += __shfl_xor_sync(0xffffffffu, v, o);
    return v;
}

// ---------------------------------------------------------------------------
// Kernel 1: logits[b,t,l] = sum_h x[b,t,h] * W[h,l] + b[l]
// warp handles 4 rows; W in shared padded to 12 floats/row.
// ---------------------------------------------------------------------------
__global__ void __launch_bounds__(256) gemm_kernel(const float* __restrict__ x,
                                                   const float* __restrict__ W,
                                                   const float* __restrict__ bias) {
    __shared__ __align__(16) float Ws[HH * 12];
    __shared__ float bs[LL];
    for (int i = threadIdx.x; i < HH * 12; i += 256) {
        int h = i / 12, l = i - h * 12;
        Ws[i] = (l < LL) ? W[h * LL + l] : 0.0f;
    }
    if (threadIdx.x < LL) bs[threadIdx.x] = bias[threadIdx.x];
    __syncthreads();

    int warp = threadIdx.x >> 5, lane = threadIdx.x & 31;
    int row0 = (blockIdx.x * 8 + warp) * 4;
    const float* xp = x + (size_t)row0 * HH;

    float acc[4][9];
    #pragma unroll
    for (int r = 0; r < 4; r++)
        #pragma unroll
        for (int l = 0; l < 9; l++) acc[r][l] = 0.0f;

    #pragma unroll
    for (int k = 0; k < 24; k++) {
        int h = lane + 32 * k;
        float xv[4];
        xv[0] = xp[h];
        xv[1] = xp[HH + h];
        xv[2] = xp[2 * HH + h];
        xv[3] = xp[3 * HH + h];
        const float* wrow = Ws + h * 12;
        float4 wa = *(const float4*)(wrow);
        float4 wb = *(const float4*)(wrow + 4);
        float  wc = wrow[8];
        #pragma unroll
        for (int r = 0; r < 4; r++) {
            acc[r][0] = fmaf(xv[r], wa.x, acc[r][0]);
            acc[r][1] = fmaf(xv[r], wa.y, acc[r][1]);
            acc[r][2] = fmaf(xv[r], wa.z, acc[r][2]);
            acc[r][3] = fmaf(xv[r], wa.w, acc[r][3]);
            acc[r][4] = fmaf(xv[r], wb.x, acc[r][4]);
            acc[r][5] = fmaf(xv[r], wb.y, acc[r][5]);
            acc[r][6] = fmaf(xv[r], wb.z, acc[r][6]);
            acc[r][7] = fmaf(xv[r], wb.w, acc[r][7]);
            acc[r][8] = fmaf(xv[r], wc,   acc[r][8]);
        }
    }

    #pragma unroll
    for (int r = 0; r < 4; r++)
        #pragma unroll
        for (int l = 0; l < 9; l++) {
            float v = acc[r][l];
            v += __shfl_xor_sync(0xffffffffu, v, 16);
            v += __shfl_xor_sync(0xffffffffu, v, 8);
            v += __shfl_xor_sync(0xffffffffu, v, 4);
            v += __shfl_xor_sync(0xffffffffu, v, 2);
            v += __shfl_xor_sync(0xffffffffu, v, 1);
            acc[r][l] = v;
        }
    if (lane < LL) {
        #pragma unroll
        for (int r = 0; r < 4; r++)
            g_logits[(size_t)(row0 + r) * LL + lane] = acc[r][lane] + bs[lane];
    }
}

// ---------------------------------------------------------------------------
// Kernel 2: per-batch CRF. warp 0 = logZ (log2 domain) + score; warp 1 =
// Viterbi + backpointers + backtrace. vit written as float into d_out.
// ---------------------------------------------------------------------------
__global__ void __launch_bounds__(64) crf_kernel(const float* __restrict__ trans,
                                                 const int* __restrict__ label,
                                                 const int* __restrict__ seqlen,
                                                 float* __restrict__ outF) {
    __shared__ __align__(16) float slog[TT * LL];
    __shared__ char sbp[TT * LL];

    int b = blockIdx.x;
    int tid = threadIdx.x, lane = tid & 31, warp = tid >> 5;
    int sl = seqlen[b];

    // stage this batch's logits (512x9 floats = 18KB)
    const float4* src = (const float4*)(g_logits + (size_t)b * TT * LL);
    float4* dst = (float4*)slog;
    for (int i = tid; i < TT * LL / 4; i += 64) dst[i] = src[i];
    __syncthreads();

    int j = (lane < LL) ? lane : (LL - 1);  // lanes >= 9 mirror state 8 (harmless)

    if (warp == 0) {
        // ---- logZ (forward logsumexp, base-2 domain) ----
        float Tj[9];
        #pragma unroll
        for (int i = 0; i < 9; i++) Tj[i] = trans[i * LL + j] * LOG2E;
        float a = slog[j] * LOG2E;

        for (int t = 1; t < sl; t++) {
            float av[9], v[9];
            #pragma unroll
            for (int i = 0; i < 9; i++) av[i] = __shfl_sync(0xffffffffu, a, i);
            #pragma unroll
            for (int i = 0; i < 9; i++) v[i] = av[i] + Tj[i];
            float m = fmaxf(fmaxf(fmaxf(v[0], v[1]), fmaxf(v[2], v[3])),
                            fmaxf(fmaxf(v[4], v[5]), fmaxf(v[6], v[7])));
            m = fmaxf(m, v[8]);
            float s = 0.0f;
            #pragma unroll
            for (int i = 0; i < 9; i++) s += ex2f_(v[i] - m);
            a = fmaf(slog[t * LL + j], LOG2E, m + lg2f_(s));
        }
        // final logsumexp over states
        float av[9];
        #pragma unroll
        for (int i = 0; i < 9; i++) av[i] = __shfl_sync(0xffffffffu, a, i);
        float m = fmaxf(fmaxf(fmaxf(av[0], av[1]), fmaxf(av[2], av[3])),
                        fmaxf(fmaxf(av[4], av[5]), fmaxf(av[6], av[7])));
        m = fmaxf(m, av[8]);
        float s = 0.0f;
        #pragma unroll
        for (int i = 0; i < 9; i++) s += ex2f_(av[i] - m);
        float logZ = (m + lg2f_(s)) * LN2;

        // ---- gold-path score ----
        const int* lab = label + b * TT;
        float sc = 0.0f;
        for (int t = lane; t < sl; t += 32) {
            int lt = lab[t];
            sc += slog[t * LL + lt];
            if (t > 0) sc += trans[lab[t - 1] * LL + lt];
        }
        sc = wredf(sc);
        if (lane == 0) g_ll[b] = logZ - sc;   // = -log-likelihood of this batch
    } else {
        // ---- Viterbi ----
        float Tj[9];
        #pragma unroll
        for (int i = 0; i < 9; i++) Tj[i] = trans[i * LL + j];
        float a = slog[j];

        for (int t = 1; t < sl; t++) {
            float av[9];
            #pragma unroll
            for (int i = 0; i < 9; i++) av[i] = __shfl_sync(0xffffffffu, a, i);
            float best = av[0] + Tj[0];
            int bi = 0;
            #pragma unroll
            for (int i = 1; i < 9; i++) {
                float v = av[i] + Tj[i];
                if (v > best) { best = v; bi = i; }   // strict >: first-max (argmax semantics)
            }
            if (lane < LL) sbp[t * LL + lane] = (char)bi;
            a = best + slog[t * LL + j];
        }
        // last = argmax (first occurrence) of final alpha
        float av[9];
        #pragma unroll
        for (int i = 0; i < 9; i++) av[i] = __shfl_sync(0xffffffffu, a, i);
        float best = av[0];
        int last = 0;
        #pragma unroll
        for (int i = 1; i < 9; i++) {
            if (av[i] > best) { best = av[i]; last = i; }
        }

        float* vout = outF + b * TT;
        // padding region: reference's identity backpointers keep tag == last
        for (int t = sl - 1 + lane; t < TT; t += 32) vout[t] = (float)last;
        if (lane == 0) {
            int tag = last;
            for (int t = sl - 2; t >= 0; t--) {
                tag = sbp[(t + 1) * LL + tag];
                vout[t] = (float)tag;
            }
        }
    }
}

// ---------------------------------------------------------------------------
// Kernel 3: scalar metrics. Reads vit back out of d_out (already written).
// ---------------------------------------------------------------------------
__global__ void __launch_bounds__(256) finalize_kernel(const int* __restrict__ label,
                                                       const int* __restrict__ seqlen,
                                                       float* __restrict__ outF) {
    __shared__ int s_sl[BB];
    __shared__ int sh_i[5][8];
    __shared__ float sh_f[8];

    int tid = threadIdx.x;
    if (tid < BB) s_sl[tid] = seqlen[tid];
    __syncthreads();

    int tp = 0, tn = 0, fp = 0, corr = 0;
    for (int i = tid; i < BB * TT; i += 256) {
        int t = i & (TT - 1);
        int bb = i >> 9;
        int la = label[i];
        int vi = __float2int_rn(outF[i]);
        bool valid = t < s_sl[bb];
        if (la > 0) { if (vi == la) tp++; else tn++; }   // NOTE: unmasked, per reference
        if (valid) {
            if (vi == la) corr++;
            if (la == 0 && vi > 0) fp++;
        }
    }
    float lsum = 0.0f;
    int slsum = 0;
    if (tid < BB) { lsum = g_ll[tid]; slsum = s_sl[tid]; }

    int warp = tid >> 5, lane = tid & 31;
    int v0 = wredi(tp), v1 = wredi(tn), v2 = wredi(fp);
    int v3 = wredi(corr);
    int v4 = wredi(slsum);
    float f0 = wredf(lsum);
    if (lane == 0) {
        sh_i[0][warp] = v0; sh_i[1][warp] = v1; sh_i[2][warp] = v2;
        sh_i[3][warp] = v3; sh_i[4][warp] = v4;
        sh_f[warp] = f0;
    }
    __syncthreads();
    if (warp == 0) {
        int a0 = (lane < 8) ? sh_i[0][lane] : 0;
        int a1 = (lane < 8) ? sh_i[1][lane] : 0;
        int a2 = (lane < 8) ? sh_i[2][lane] : 0;
        int a3 = (lane < 8) ? sh_i[3][lane] : 0;
        int a4 = (lane < 8) ? sh_i[4][lane] : 0;
        float af = (lane < 8) ? sh_f[lane] : 0.0f;
        a0 = wredi(a0); a1 = wredi(a1); a2 = wredi(a2); a3 = wredi(a3); a4 = wredi(a4);
        af = wredf(af);
        if (lane == 0) {
            outF[BB * TT + 0] = (float)a0;              // tp
            outF[BB * TT + 1] = (float)a1;              // tn
            outF[BB * TT + 2] = (float)a2;              // fp
            outF[BB * TT + 3] = af / (float)BB;         // loss
            outF[BB * TT + 4] = (float)a3 / (float)a4;  // accuracy
        }
    }
}

// ---------------------------------------------------------------------------
extern "C" void kernel_launch(void* const* d_in, const int* in_sizes, int n_in,
                              void* d_out, int out_size) {
    const float* x      = (const float*)d_in[0];
    const float* W      = (const float*)d_in[1];
    const float* bias   = (const float*)d_in[2];
    const float* trans  = (const float*)d_in[3];
    const int*   label  = (const int*)d_in[4];
    const int*   seqlen = (const int*)d_in[5];
    float* out = (float*)d_out;

    gemm_kernel<<<1024, 256>>>(x, W, bias);
    crf_kernel<<<BB, 64>>>(trans, label, seqlen, out);
    finalize_kernel<<<1, 256>>>(label, seqlen, out);
}

// round 5
// speedup vs baseline: 1.6013x; 1.6013x over previous
#include <cuda_runtime.h>

#define BB 64
#define TT 512
#define HH 768
#define LL 9
#define LOG2E 1.4426950408889634f
#define LN2   0.6931471805599453f

__device__ __align__(16) float g_logits[BB * TT * LL];
__device__ float g_ll[BB];
__device__ float g_red[4];   // tp, tn, fp, corr

__device__ __forceinline__ float ex2f_(float x) {
    float y; asm("ex2.approx.ftz.f32 %0, %1;" : "=f"(y) : "f"(x)); return y;
}
__device__ __forceinline__ float lg2f_(float x) {
    float y; asm("lg2.approx.ftz.f32 %0, %1;" : "=f"(y) : "f"(x)); return y;
}
__device__ __forceinline__ int wredi(int v) {
    #pragma unroll
    for (int o = 16; o; o >>= 1) v += __shfl_xor_sync(0xffffffffu, v, o);
    return v;
}
__device__ __forceinline__ float wredf(float v) {
    #pragma unroll
    for (int o = 16; o; o >>= 1) v += __shfl_xor_sync(0xffffffffu, v, o);
    return v;
}

// ---------------------------------------------------------------------------
// Kernel 1: logits = x@W + b.  Packed fma.rn.f32x2: 5 packed FMA per row-k
// instead of 9 scalar FFMA. Accs: pairs (l0,l1)(l2,l3)(l4,l5)(l6,l7)(l8,pad).
// ---------------------------------------------------------------------------
__global__ void __launch_bounds__(256) gemm_kernel(const float* __restrict__ x,
                                                   const float* __restrict__ W,
                                                   const float* __restrict__ bias) {
    __shared__ __align__(16) float Ws[HH * 12];
    __shared__ float bs[LL];
    for (int i = threadIdx.x; i < HH * 12; i += 256) {
        int h = i / 12, l = i - h * 12;
        Ws[i] = (l < LL) ? W[h * LL + l] : 0.0f;
    }
    if (threadIdx.x < LL) bs[threadIdx.x] = bias[threadIdx.x];
    __syncthreads();

    int warp = threadIdx.x >> 5, lane = threadIdx.x & 31;
    int row0 = (blockIdx.x * 8 + warp) * 4;
    const float* xp = x + (size_t)row0 * HH;

    unsigned long long acc[4][5];
    #pragma unroll
    for (int r = 0; r < 4; r++)
        #pragma unroll
        for (int p = 0; p < 5; p++) acc[r][p] = 0ull;

    #pragma unroll
    for (int k = 0; k < 24; k++) {
        int h = lane + 32 * k;
        float xv[4];
        xv[0] = xp[h];
        xv[1] = xp[HH + h];
        xv[2] = xp[2 * HH + h];
        xv[3] = xp[3 * HH + h];
        const float* wrow = Ws + h * 12;
        ulonglong2 wa = *(const ulonglong2*)(wrow);       // (w0,w1),(w2,w3)
        ulonglong2 wb = *(const ulonglong2*)(wrow + 4);   // (w4,w5),(w6,w7)
        unsigned long long w8p = *(const unsigned long long*)(wrow + 8);  // (w8, 0)
        #pragma unroll
        for (int r = 0; r < 4; r++) {
            unsigned long long x2;
            asm("mov.b64 %0, {%1,%1};" : "=l"(x2) : "f"(xv[r]));
            asm("fma.rn.f32x2 %0, %1, %2, %0;" : "+l"(acc[r][0]) : "l"(x2), "l"(wa.x));
            asm("fma.rn.f32x2 %0, %1, %2, %0;" : "+l"(acc[r][1]) : "l"(x2), "l"(wa.y));
            asm("fma.rn.f32x2 %0, %1, %2, %0;" : "+l"(acc[r][2]) : "l"(x2), "l"(wb.x));
            asm("fma.rn.f32x2 %0, %1, %2, %0;" : "+l"(acc[r][3]) : "l"(x2), "l"(wb.y));
            asm("fma.rn.f32x2 %0, %1, %2, %0;" : "+l"(acc[r][4]) : "l"(x2), "l"(w8p));
        }
    }

    #pragma unroll
    for (int r = 0; r < 4; r++) {
        float a[9];
        #pragma unroll
        for (int p = 0; p < 4; p++) {
            float lo, hi;
            asm("mov.b64 {%0,%1}, %2;" : "=f"(lo), "=f"(hi) : "l"(acc[r][p]));
            a[2 * p] = lo; a[2 * p + 1] = hi;
        }
        { float lo, hi;
          asm("mov.b64 {%0,%1}, %2;" : "=f"(lo), "=f"(hi) : "l"(acc[r][4]));
          a[8] = lo; (void)hi; }
        #pragma unroll
        for (int l = 0; l < 9; l++) {
            float v = a[l];
            v += __shfl_xor_sync(0xffffffffu, v, 16);
            v += __shfl_xor_sync(0xffffffffu, v, 8);
            v += __shfl_xor_sync(0xffffffffu, v, 4);
            v += __shfl_xor_sync(0xffffffffu, v, 2);
            v += __shfl_xor_sync(0xffffffffu, v, 1);
            a[l] = v;
        }
        if (lane < LL)
            g_logits[(size_t)(row0 + r) * LL + lane] = a[lane] + bs[lane];
    }
}

// ---------------------------------------------------------------------------
// Kernel 2: per-batch CRF, 128 threads.
//  warp 0: scaled-forward logZ (exp domain, no MUFU on critical path) + score
//  warp 1: Viterbi forward (pure fmax tree, alphas -> smem)
//  all:    parallel backpointer recompute, then serial backtrace.
// ---------------------------------------------------------------------------
__global__ void __launch_bounds__(128) crf_kernel(const float* __restrict__ trans,
                                                  const int* __restrict__ label,
                                                  const int* __restrict__ seqlen,
                                                  float* __restrict__ outF) {
    __shared__ __align__(16) float slog[TT * LL];     // 18 KB
    __shared__ __align__(16) float astore[TT * LL];   // 18 KB
    __shared__ unsigned char sbp[TT * LL];            // 4.5 KB
    __shared__ float Ts[LL * LL];
    __shared__ int s_lasti;

    int b = blockIdx.x;
    int tid = threadIdx.x, lane = tid & 31, warp = tid >> 5;
    int sl = seqlen[b];

    if (b == 0 && tid < 4) g_red[tid] = 0.0f;   // zero global accumulators

    // stage logits (18KB) + transitions
    {
        const float4* src = (const float4*)(g_logits + (size_t)b * TT * LL);
        float4* dst = (float4*)slog;
        for (int i = tid; i < TT * LL / 4; i += 128) dst[i] = src[i];
        if (tid < LL * LL) Ts[tid] = trans[tid];
    }
    __syncthreads();

    int j = (lane < LL) ? lane : (LL - 1);

    if (warp == 0) {
        // ---- scaled-forward logZ ----
        float P[9];
        #pragma unroll
        for (int i = 0; i < 9; i++) P[i] = ex2f_(Ts[i * LL + j] * LOG2E);
        float p0 = slog[0] * LOG2E;                 // pivot (uniform, from smem)
        float c = ex2f_(slog[j] * LOG2E - p0);
        int S = 0;
        float w = ex2f_(slog[LL + j] * LOG2E);      // prefetched w for t=1

        for (int t = 1; t < sl; t++) {
            float cv[9];
            #pragma unroll
            for (int i = 0; i < 9; i++) cv[i] = __shfl_sync(0xffffffffu, c, i);
            // prefetch next w (off critical path)
            int tn = (t + 1 < TT) ? (t + 1) : (TT - 1);
            float wn = ex2f_(slog[tn * LL + j] * LOG2E);
            // rescale factor from cv[0] exponent (pure ALU)
            unsigned bits = __float_as_uint(cv[0]);
            int e = (int)(bits >> 23) - 127;
            float factor = __uint_as_float((unsigned)(127 - e) << 23);
            S += e;
            // dot with P column (mul + tree add)
            float m0 = cv[0] * P[0], m1 = cv[1] * P[1], m2 = cv[2] * P[2],
                  m3 = cv[3] * P[3], m4 = cv[4] * P[4], m5 = cv[5] * P[5],
                  m6 = cv[6] * P[6], m7 = cv[7] * P[7], m8 = cv[8] * P[8];
            float u = ((m0 + m1) + (m2 + m3)) + (((m4 + m5) + (m6 + m7)) + m8);
            c = u * factor * w;
            w = wn;
        }
        float cv[9];
        #pragma unroll
        for (int i = 0; i < 9; i++) cv[i] = __shfl_sync(0xffffffffu, c, i);
        float sum = ((cv[0] + cv[1]) + (cv[2] + cv[3]))
                  + (((cv[4] + cv[5]) + (cv[6] + cv[7])) + cv[8]);
        float logZ = (lg2f_(sum) + (float)S + p0) * LN2;

        // ---- gold-path score ----
        const int* lab = label + b * TT;
        float sc = 0.0f;
        for (int t = lane; t < sl; t += 32) {
            int lt = lab[t];
            sc += slog[t * LL + lt];
            if (t > 0) sc += Ts[lab[t - 1] * LL + lt];
        }
        sc = wredf(sc);
        if (lane == 0) g_ll[b] = logZ - sc;
    } else if (warp == 1) {
        // ---- Viterbi forward (no argmax inside the chain) ----
        float Tj[9];
        #pragma unroll
        for (int i = 0; i < 9; i++) Tj[i] = Ts[i * LL + j];
        float a = slog[j];
        if (lane < LL) astore[j] = a;

        for (int t = 1; t < sl; t++) {
            float av[9];
            #pragma unroll
            for (int i = 0; i < 9; i++) av[i] = __shfl_sync(0xffffffffu, a, i);
            float v0 = av[0] + Tj[0], v1 = av[1] + Tj[1], v2 = av[2] + Tj[2],
                  v3 = av[3] + Tj[3], v4 = av[4] + Tj[4], v5 = av[5] + Tj[5],
                  v6 = av[6] + Tj[6], v7 = av[7] + Tj[7], v8 = av[8] + Tj[8];
            float best = fmaxf(fmaxf(fmaxf(v0, v1), fmaxf(v2, v3)),
                               fmaxf(fmaxf(fmaxf(v4, v5), fmaxf(v6, v7)), v8));
            a = best + slog[t * LL + j];
            if (lane < LL) astore[t * LL + lane] = a;
        }
        // last = first-max argmax of final alpha
        float av[9];
        #pragma unroll
        for (int i = 0; i < 9; i++) av[i] = __shfl_sync(0xffffffffu, a, i);
        float best = av[0];
        int last = 0;
        #pragma unroll
        for (int i = 1; i < 9; i++)
            if (av[i] > best) { best = av[i]; last = i; }
        if (lane == 0) s_lasti = last;
    }
    __syncthreads();

    // ---- parallel backpointer recompute: bp[t][j] = argmax_i(astore[t-1][i]+T[i][j])
    if (tid < 126) {
        int jj = tid % 9, g = tid / 9;    // 14 groups
        float Tc[9];
        #pragma unroll
        for (int i = 0; i < 9; i++) Tc[i] = Ts[i * LL + jj];
        for (int t = 1 + g; t < sl; t += 14) {
            const float* ap = astore + (t - 1) * LL;
            float bv = ap[0] + Tc[0];
            int bi = 0;
            #pragma unroll
            for (int i = 1; i < 9; i++) {
                float v = ap[i] + Tc[i];
                if (v > bv) { bv = v; bi = i; }
            }
            sbp[t * LL + jj] = (unsigned char)bi;
        }
    }
    __syncthreads();

    // ---- backtrace + output ----
    int last = s_lasti;
    float* vout = outF + b * TT;
    for (int t = sl - 1 + tid; t < TT; t += 128) vout[t] = (float)last;
    if (tid == 0) {
        int tag = last;
        for (int t = sl - 2; t >= 0; t--) {
            tag = sbp[(t + 1) * LL + tag];
            vout[t] = (float)tag;
        }
    }
}

// ---------------------------------------------------------------------------
// Kernel 3a: partial metric reduction (8 blocks), atomics into g_red.
// ---------------------------------------------------------------------------
__global__ void __launch_bounds__(256) finalize_partial(const int* __restrict__ label,
                                                        const int* __restrict__ seqlen,
                                                        const float* __restrict__ outF) {
    __shared__ int s_sl[BB];
    __shared__ int sh_i[4][8];

    int tid = threadIdx.x;
    if (tid < BB) s_sl[tid] = seqlen[tid];
    __syncthreads();

    int tp = 0, tn = 0, fp = 0, corr = 0;
    for (int i = blockIdx.x * 256 + tid; i < BB * TT; i += 8 * 256) {
        int t = i & (TT - 1);
        int bb = i >> 9;
        int la = label[i];
        int vi = __float2int_rn(outF[i]);
        if (la > 0) { if (vi == la) tp++; else tn++; }   // unmasked, per reference
        if (t < s_sl[bb]) {
            if (vi == la) corr++;
            if (la == 0 && vi > 0) fp++;
        }
    }
    int warp = tid >> 5, lane = tid & 31;
    int v0 = wredi(tp), v1 = wredi(tn), v2 = wredi(fp), v3 = wredi(corr);
    if (lane == 0) { sh_i[0][warp] = v0; sh_i[1][warp] = v1; sh_i[2][warp] = v2; sh_i[3][warp] = v3; }
    __syncthreads();
    if (warp == 0) {
        int a0 = (lane < 8) ? sh_i[0][lane] : 0;
        int a1 = (lane < 8) ? sh_i[1][lane] : 0;
        int a2 = (lane < 8) ? sh_i[2][lane] : 0;
        int a3 = (lane < 8) ? sh_i[3][lane] : 0;
        a0 = wredi(a0); a1 = wredi(a1); a2 = wredi(a2); a3 = wredi(a3);
        if (lane == 0) {
            atomicAdd(&g_red[0], (float)a0);
            atomicAdd(&g_red[1], (float)a1);
            atomicAdd(&g_red[2], (float)a2);
            atomicAdd(&g_red[3], (float)a3);
        }
    }
}

// ---------------------------------------------------------------------------
// Kernel 3b: final scalar write.
// ---------------------------------------------------------------------------
__global__ void __launch_bounds__(32) finalize_write(const int* __restrict__ seqlen,
                                                     float* __restrict__ outF) {
    int lane = threadIdx.x;
    float lsum = g_ll[lane] + g_ll[lane + 32];
    int sls = seqlen[lane] + seqlen[lane + 32];
    lsum = wredf(lsum);
    sls = wredi(sls);
    if (lane == 0) {
        outF[BB * TT + 0] = g_red[0];                    // tp
        outF[BB * TT + 1] = g_red[1];                    // tn
        outF[BB * TT + 2] = g_red[2];                    // fp
        outF[BB * TT + 3] = lsum / (float)BB;            // loss
        outF[BB * TT + 4] = g_red[3] / (float)sls;       // accuracy
    }
}

// ---------------------------------------------------------------------------
extern "C" void kernel_launch(void* const* d_in, const int* in_sizes, int n_in,
                              void* d_out, int out_size) {
    const float* x      = (const float*)d_in[0];
    const float* W      = (const float*)d_in[1];
    const float* bias   = (const float*)d_in[2];
    const float* trans  = (const float*)d_in[3];
    const int*   label  = (const int*)d_in[4];
    const int*   seqlen = (const int*)d_in[5];
    float* out = (float*)d_out;

    gemm_kernel<<<1024, 256>>>(x, W, bias);
    crf_kernel<<<BB, 128>>>(trans, label, seqlen, out);
    finalize_partial<<<8, 256>>>(label, seqlen, out);
    finalize_write<<<1, 32>>>(seqlen, out);
}

// round 6
// speedup vs baseline: 2.3208x; 1.4494x over previous
#include <cuda_runtime.h>

#define BB 64
#define TT 512
#define HH 768
#define LL 9
#define LOG2E 1.4426950408889634f
#define LN2   0.6931471805599453f

__device__ __align__(16) float g_logits[BB * TT * LL];
__device__ float g_ll[BB];
__device__ float g_red[4];   // tp, tn, fp, corr
__device__ int   g_tick;     // completion ticket (zero-init; reset by last block)

__device__ __forceinline__ float ex2f_(float x) {
    float y; asm("ex2.approx.ftz.f32 %0, %1;" : "=f"(y) : "f"(x)); return y;
}
__device__ __forceinline__ float lg2f_(float x) {
    float y; asm("lg2.approx.ftz.f32 %0, %1;" : "=f"(y) : "f"(x)); return y;
}
__device__ __forceinline__ int wredi(int v) {
    #pragma unroll
    for (int o = 16; o; o >>= 1) v += __shfl_xor_sync(0xffffffffu, v, o);
    return v;
}
__device__ __forceinline__ float wredf(float v) {
    #pragma unroll
    for (int o = 16; o; o >>= 1) v += __shfl_xor_sync(0xffffffffu, v, o);
    return v;
}

// map composition: (F o G)(x) = F(G(x)); maps are 9 nibbles packed in uint64
#define MAP_IDENTITY 0x876543210ull
__device__ __forceinline__ unsigned long long map_compose(unsigned long long F,
                                                          unsigned long long G) {
    unsigned long long h = 0;
    #pragma unroll
    for (int i = 0; i < 9; i++) {
        int gi = (int)((G >> (4 * i)) & 15ull);
        unsigned long long fi = (F >> (gi * 4)) & 15ull;
        h |= fi << (4 * i);
    }
    return h;
}

// ---------------------------------------------------------------------------
// Kernel 1: logits = x@W + b.  float4 x loads, W unpadded (9 f/row) in smem,
// packed fma.rn.f32x2.  Warp: 4 rows; kk loop: 4 h per lane per iter.
// Block 0 also zeroes the global accumulators (runs before any crf atomic).
// ---------------------------------------------------------------------------
__global__ void __launch_bounds__(256) gemm_kernel(const float* __restrict__ x,
                                                   const float* __restrict__ W,
                                                   const float* __restrict__ bias) {
    __shared__ __align__(16) float Ws[HH * 9];   // 27648 B
    __shared__ float bs[LL];

    if (blockIdx.x == 0 && threadIdx.x < 4) g_red[threadIdx.x] = 0.0f;

    {
        const float4* src = (const float4*)W;
        float4* dst = (float4*)Ws;
        for (int i = threadIdx.x; i < HH * 9 / 4; i += 256) dst[i] = src[i];
    }
    if (threadIdx.x < LL) bs[threadIdx.x] = bias[threadIdx.x];
    __syncthreads();

    int warp = threadIdx.x >> 5, lane = threadIdx.x & 31;
    int row0 = (blockIdx.x * 8 + warp) * 4;
    const float* xp = x + (size_t)row0 * HH;

    unsigned long long acc[4][5];
    #pragma unroll
    for (int r = 0; r < 4; r++)
        #pragma unroll
        for (int p = 0; p < 5; p++) acc[r][p] = 0ull;

    #pragma unroll
    for (int kk = 0; kk < 6; kk++) {
        int h0 = lane * 4 + 128 * kk;
        // x: one float4 per row
        float4 xr[4];
        xr[0] = *(const float4*)(xp + h0);
        xr[1] = *(const float4*)(xp + HH + h0);
        xr[2] = *(const float4*)(xp + 2 * HH + h0);
        xr[3] = *(const float4*)(xp + 3 * HH + h0);
        // W rows h0..h0+3 : 36 consecutive floats, 16B-aligned
        float wf[36];
        {
            const float4* wp = (const float4*)(Ws + h0 * 9);
            #pragma unroll
            for (int i = 0; i < 9; i++) ((float4*)wf)[i] = wp[i];
        }
        #pragma unroll
        for (int d = 0; d < 4; d++) {
            const float* wr = wf + 9 * d;
            unsigned long long w0, w1, w2, w3, w4p;
            asm("mov.b64 %0, {%1,%2};" : "=l"(w0) : "f"(wr[0]), "f"(wr[1]));
            asm("mov.b64 %0, {%1,%2};" : "=l"(w1) : "f"(wr[2]), "f"(wr[3]));
            asm("mov.b64 %0, {%1,%2};" : "=l"(w2) : "f"(wr[4]), "f"(wr[5]));
            asm("mov.b64 %0, {%1,%2};" : "=l"(w3) : "f"(wr[6]), "f"(wr[7]));
            asm("mov.b64 %0, {%1,%2};" : "=l"(w4p) : "f"(wr[8]), "f"(0.0f));
            #pragma unroll
            for (int r = 0; r < 4; r++) {
                float xv = (d == 0) ? xr[r].x : (d == 1) ? xr[r].y
                         : (d == 2) ? xr[r].z : xr[r].w;
                unsigned long long x2;
                asm("mov.b64 %0, {%1,%1};" : "=l"(x2) : "f"(xv));
                asm("fma.rn.f32x2 %0, %1, %2, %0;" : "+l"(acc[r][0]) : "l"(x2), "l"(w0));
                asm("fma.rn.f32x2 %0, %1, %2, %0;" : "+l"(acc[r][1]) : "l"(x2), "l"(w1));
                asm("fma.rn.f32x2 %0, %1, %2, %0;" : "+l"(acc[r][2]) : "l"(x2), "l"(w2));
                asm("fma.rn.f32x2 %0, %1, %2, %0;" : "+l"(acc[r][3]) : "l"(x2), "l"(w3));
                asm("fma.rn.f32x2 %0, %1, %2, %0;" : "+l"(acc[r][4]) : "l"(x2), "l"(w4p));
            }
        }
    }

    #pragma unroll
    for (int r = 0; r < 4; r++) {
        float a[9];
        #pragma unroll
        for (int p = 0; p < 4; p++) {
            float lo, hi;
            asm("mov.b64 {%0,%1}, %2;" : "=f"(lo), "=f"(hi) : "l"(acc[r][p]));
            a[2 * p] = lo; a[2 * p + 1] = hi;
        }
        { float lo, hi;
          asm("mov.b64 {%0,%1}, %2;" : "=f"(lo), "=f"(hi) : "l"(acc[r][4]));
          a[8] = lo; (void)hi; }
        #pragma unroll
        for (int l = 0; l < 9; l++) {
            float v = a[l];
            v += __shfl_xor_sync(0xffffffffu, v, 16);
            v += __shfl_xor_sync(0xffffffffu, v, 8);
            v += __shfl_xor_sync(0xffffffffu, v, 4);
            v += __shfl_xor_sync(0xffffffffu, v, 2);
            v += __shfl_xor_sync(0xffffffffu, v, 1);
            a[l] = v;
        }
        if (lane < LL)
            g_logits[(size_t)(row0 + r) * LL + lane] = a[lane] + bs[lane];
    }
}

// ---------------------------------------------------------------------------
// Kernel 2: per-batch CRF + fused metrics + last-block scalar write.
// ---------------------------------------------------------------------------
__global__ void __launch_bounds__(128) crf_kernel(const float* __restrict__ trans,
                                                  const int* __restrict__ label,
                                                  const int* __restrict__ seqlen,
                                                  float* __restrict__ outF) {
    __shared__ __align__(16) float slog[TT * LL];     // 18 KB
    __shared__ __align__(16) float astore[TT * LL];   // 18 KB
    __shared__ unsigned char sbp[TT * LL];            // 4.5 KB
    __shared__ unsigned char stag[TT];                // 0.5 KB
    __shared__ float Ts[LL * LL];
    __shared__ int s_lasti;
    __shared__ int s_isLast;

    int b = blockIdx.x;
    int tid = threadIdx.x, lane = tid & 31, warp = tid >> 5;
    int sl = seqlen[b];

    // stage logits + transitions
    {
        const float4* src = (const float4*)(g_logits + (size_t)b * TT * LL);
        float4* dst = (float4*)slog;
        for (int i = tid; i < TT * LL / 4; i += 128) dst[i] = src[i];
        if (tid < LL * LL) Ts[tid] = trans[tid];
    }
    __syncthreads();

    int j = (lane < LL) ? lane : (LL - 1);

    if (warp == 0) {
        // ---- scaled-forward logZ (exp domain, MUFU off critical path) ----
        float P[9];
        #pragma unroll
        for (int i = 0; i < 9; i++) P[i] = ex2f_(Ts[i * LL + j] * LOG2E);
        float p0 = slog[0] * LOG2E;
        float c = ex2f_(slog[j] * LOG2E - p0);
        int S = 0;
        float w = ex2f_(slog[LL + j] * LOG2E);

        for (int t = 1; t < sl; t++) {
            float cv[9];
            #pragma unroll
            for (int i = 0; i < 9; i++) cv[i] = __shfl_sync(0xffffffffu, c, i);
            int tn = (t + 1 < TT) ? (t + 1) : (TT - 1);
            float wn = ex2f_(slog[tn * LL + j] * LOG2E);
            unsigned bits = __float_as_uint(cv[0]);
            int e = (int)(bits >> 23) - 127;
            float factor = __uint_as_float((unsigned)(127 - e) << 23);
            S += e;
            float m0 = cv[0] * P[0], m1 = cv[1] * P[1], m2 = cv[2] * P[2],
                  m3 = cv[3] * P[3], m4 = cv[4] * P[4], m5 = cv[5] * P[5],
                  m6 = cv[6] * P[6], m7 = cv[7] * P[7], m8 = cv[8] * P[8];
            float u = ((m0 + m1) + (m2 + m3)) + (((m4 + m5) + (m6 + m7)) + m8);
            c = u * factor * w;
            w = wn;
        }
        float cv[9];
        #pragma unroll
        for (int i = 0; i < 9; i++) cv[i] = __shfl_sync(0xffffffffu, c, i);
        float sum = ((cv[0] + cv[1]) + (cv[2] + cv[3]))
                  + (((cv[4] + cv[5]) + (cv[6] + cv[7])) + cv[8]);
        float logZ = (lg2f_(sum) + (float)S + p0) * LN2;

        // ---- gold-path score ----
        const int* lab = label + b * TT;
        float sc = 0.0f;
        for (int t = lane; t < sl; t += 32) {
            int lt = lab[t];
            sc += slog[t * LL + lt];
            if (t > 0) sc += Ts[lab[t - 1] * LL + lt];
        }
        sc = wredf(sc);
        if (lane == 0) g_ll[b] = logZ - sc;
    } else if (warp == 1) {
        // ---- Viterbi forward (pure fmax tree; alphas to smem) ----
        float Tj[9];
        #pragma unroll
        for (int i = 0; i < 9; i++) Tj[i] = Ts[i * LL + j];
        float a = slog[j];
        if (lane < LL) astore[j] = a;

        for (int t = 1; t < sl; t++) {
            float av[9];
            #pragma unroll
            for (int i = 0; i < 9; i++) av[i] = __shfl_sync(0xffffffffu, a, i);
            float v0 = av[0] + Tj[0], v1 = av[1] + Tj[1], v2 = av[2] + Tj[2],
                  v3 = av[3] + Tj[3], v4 = av[4] + Tj[4], v5 = av[5] + Tj[5],
                  v6 = av[6] + Tj[6], v7 = av[7] + Tj[7], v8 = av[8] + Tj[8];
            float best = fmaxf(fmaxf(fmaxf(v0, v1), fmaxf(v2, v3)),
                               fmaxf(fmaxf(fmaxf(v4, v5), fmaxf(v6, v7)), v8));
            a = best + slog[t * LL + j];
            if (lane < LL) astore[t * LL + lane] = a;
        }
        float av[9];
        #pragma unroll
        for (int i = 0; i < 9; i++) av[i] = __shfl_sync(0xffffffffu, a, i);
        float best = av[0];
        int last = 0;
        #pragma unroll
        for (int i = 1; i < 9; i++)
            if (av[i] > best) { best = av[i]; last = i; }
        if (lane == 0) s_lasti = last;
    }
    __syncthreads();

    // ---- parallel backpointer recompute: bp[t][j] = argmax_i(alpha[t-1][i]+T[i][j])
    if (tid < 126) {
        int jj = tid % 9, g = tid / 9;    // 14 groups
        float Tc[9];
        #pragma unroll
        for (int i = 0; i < 9; i++) Tc[i] = Ts[i * LL + jj];
        for (int t = 1 + g; t < sl; t += 14) {
            const float* ap = astore + (t - 1) * LL;
            float bv = ap[0] + Tc[0];
            int bi = 0;
            #pragma unroll
            for (int i = 1; i < 9; i++) {
                float v = ap[i] + Tc[i];
                if (v > bv) { bv = v; bi = i; }
            }
            sbp[t * LL + jj] = (unsigned char)bi;
        }
    }
    __syncthreads();

    int last = s_lasti;
    // padding tags
    for (int t = sl - 1 + tid; t < TT; t += 128) stag[t] = (unsigned char)last;

    // ---- parallel backtrace: suffix scan of backpointer maps (warp 0) ----
    if (warp == 0 && sl > 1) {
        int N = sl - 1;                       // maps at t = 1..sl-1
        int C = (N + 31) >> 5;                // chunk per lane
        int a0 = 1 + lane * C;
        int b0 = min(a0 + C, sl);
        unsigned long long P = MAP_IDENTITY;
        for (int m = a0; m < b0; m++) {
            const unsigned char* row = sbp + m * LL;
            unsigned long long f = 0;
            #pragma unroll
            for (int i = 0; i < 9; i++)
                f |= (unsigned long long)row[i] << (4 * i);
            P = map_compose(P, f);            // P = f_a o ... o f_m
        }
        // inclusive suffix scan across lanes
        #pragma unroll
        for (int off = 1; off < 32; off <<= 1) {
            unsigned long long q = __shfl_down_sync(0xffffffffu, P, off);
            if (lane + off < 32) P = map_compose(P, q);
        }
        unsigned long long R = __shfl_down_sync(0xffffffffu, P, 1);
        if (lane == 31) R = MAP_IDENTITY;
        // walk own segment backwards
        if (a0 < sl) {
            int xcur = (int)((R >> (4 * last)) & 15ull);   // tag at b0-1
            for (int m = b0 - 1; m >= a0; m--) {
                xcur = sbp[m * LL + xcur];
                stag[m - 1] = (unsigned char)xcur;
            }
        }
    }
    __syncthreads();

    // ---- vit output (coalesced) + fused metrics ----
    float* vout = outF + b * TT;
    const int* lab = label + b * TT;
    int tp = 0, tn = 0, fp = 0, corr = 0;
    for (int i = tid; i < TT; i += 128) {
        int vi = stag[i];
        vout[i] = (float)vi;
        int la = lab[i];
        if (la > 0) { if (vi == la) tp++; else tn++; }   // unmasked, per reference
        if (i < sl) {
            if (vi == la) corr++;
            if (la == 0 && vi > 0) fp++;
        }
    }
    tp = wredi(tp); tn = wredi(tn); fp = wredi(fp); corr = wredi(corr);
    if (lane == 0) {
        atomicAdd(&g_red[0], (float)tp);
        atomicAdd(&g_red[1], (float)tn);
        atomicAdd(&g_red[2], (float)fp);
        atomicAdd(&g_red[3], (float)corr);
    }

    // ---- completion ticket; last block writes scalars ----
    __threadfence();
    __syncthreads();
    if (tid == 0) {
        int old = atomicAdd(&g_tick, 1);
        s_isLast = (old == BB - 1);
    }
    __syncthreads();
    if (s_isLast && warp == 0) {
        __threadfence();
        float lsum = g_ll[lane] + g_ll[lane + 32];
        int sls = seqlen[lane] + seqlen[lane + 32];
        lsum = wredf(lsum);
        sls = wredi(sls);
        if (lane == 0) {
            outF[BB * TT + 0] = g_red[0];                 // tp
            outF[BB * TT + 1] = g_red[1];                 // tn
            outF[BB * TT + 2] = g_red[2];                 // fp
            outF[BB * TT + 3] = lsum / (float)BB;         // loss
            outF[BB * TT + 4] = g_red[3] / (float)sls;    // accuracy
            g_tick = 0;                                   // reset for next replay
        }
    }
}

// ---------------------------------------------------------------------------
extern "C" void kernel_launch(void* const* d_in, const int* in_sizes, int n_in,
                              void* d_out, int out_size) {
    const float* x      = (const float*)d_in[0];
    const float* W      = (const float*)d_in[1];
    const float* bias   = (const float*)d_in[2];
    const float* trans  = (const float*)d_in[3];
    const int*   label  = (const int*)d_in[4];
    const int*   seqlen = (const int*)d_in[5];
    float* out = (float*)d_out;

    gemm_kernel<<<1024, 256>>>(x, W, bias);
    crf_kernel<<<BB, 128>>>(trans, label, seqlen, out);
}

// round 7
// speedup vs baseline: 2.3510x; 1.0130x over previous
#include <cuda_runtime.h>

#define BB 64
#define TT 512
#define HH 768
#define LL 9
#define NG 10
#define LOG2E 1.4426950408889634f
#define LN2   0.6931471805599453f

__device__ __align__(16) float g_logits[BB * TT * LL];
__device__ float g_ll[BB];
__device__ float g_red[4];   // tp, tn, fp, corr
__device__ int   g_tick;     // completion ticket (zero-init; reset by last block)

__device__ __forceinline__ float ex2f_(float x) {
    float y; asm("ex2.approx.ftz.f32 %0, %1;" : "=f"(y) : "f"(x)); return y;
}
__device__ __forceinline__ float lg2f_(float x) {
    float y; asm("lg2.approx.ftz.f32 %0, %1;" : "=f"(y) : "f"(x)); return y;
}
__device__ __forceinline__ int wredi(int v) {
    #pragma unroll
    for (int o = 16; o; o >>= 1) v += __shfl_xor_sync(0xffffffffu, v, o);
    return v;
}
__device__ __forceinline__ float wredf(float v) {
    #pragma unroll
    for (int o = 16; o; o >>= 1) v += __shfl_xor_sync(0xffffffffu, v, o);
    return v;
}

// map composition for backtrace: (F o G)(x) = F(G(x)); 9 nibbles in uint64
#define MAP_IDENTITY 0x876543210ull
__device__ __forceinline__ unsigned long long map_compose(unsigned long long F,
                                                          unsigned long long G) {
    unsigned long long h = 0;
    #pragma unroll
    for (int i = 0; i < 9; i++) {
        int gi = (int)((G >> (4 * i)) & 15ull);
        unsigned long long fi = (F >> (gi * 4)) & 15ull;
        h |= fi << (4 * i);
    }
    return h;
}

struct CrfSmem {
    float slog[TT * LL];          // raw logits (fp32, exact for Viterbi/score)
    float astore[TT * LL];        // Viterbi alphas
    float swexp[TT * LL];         // 2^(logit*log2e) for logZ chunks
    float Ts[LL * LL];            // transitions
    float sP[LL * LL];            // exp(transitions)
    float sM[NG][LL][LL];         // chunk matrices  sM[g][m][j]
    int   sE[NG][LL];             // per-column exponents
    int   sEg[NG];                // per-chunk max exponent
    unsigned char sbp[TT * LL];   // backpointers
    unsigned char stag[TT];       // decoded tags
    float s_logZ;
    int   s_lasti;
    int   s_isLast;
};

// ---------------------------------------------------------------------------
// Kernel 1: logits = x@W + b (float4 x, packed fma.rn.f32x2). Unchanged (R6).
// ---------------------------------------------------------------------------
__global__ void __launch_bounds__(256) gemm_kernel(const float* __restrict__ x,
                                                   const float* __restrict__ W,
                                                   const float* __restrict__ bias) {
    __shared__ __align__(16) float Ws[HH * 9];
    __shared__ float bs[LL];

    if (blockIdx.x == 0 && threadIdx.x < 4) g_red[threadIdx.x] = 0.0f;

    {
        const float4* src = (const float4*)W;
        float4* dst = (float4*)Ws;
        for (int i = threadIdx.x; i < HH * 9 / 4; i += 256) dst[i] = src[i];
    }
    if (threadIdx.x < LL) bs[threadIdx.x] = bias[threadIdx.x];
    __syncthreads();

    int warp = threadIdx.x >> 5, lane = threadIdx.x & 31;
    int row0 = (blockIdx.x * 8 + warp) * 4;
    const float* xp = x + (size_t)row0 * HH;

    unsigned long long acc[4][5];
    #pragma unroll
    for (int r = 0; r < 4; r++)
        #pragma unroll
        for (int p = 0; p < 5; p++) acc[r][p] = 0ull;

    #pragma unroll
    for (int kk = 0; kk < 6; kk++) {
        int h0 = lane * 4 + 128 * kk;
        float4 xr[4];
        xr[0] = *(const float4*)(xp + h0);
        xr[1] = *(const float4*)(xp + HH + h0);
        xr[2] = *(const float4*)(xp + 2 * HH + h0);
        xr[3] = *(const float4*)(xp + 3 * HH + h0);
        float wf[36];
        {
            const float4* wp = (const float4*)(Ws + h0 * 9);
            #pragma unroll
            for (int i = 0; i < 9; i++) ((float4*)wf)[i] = wp[i];
        }
        #pragma unroll
        for (int d = 0; d < 4; d++) {
            const float* wr = wf + 9 * d;
            unsigned long long w0, w1, w2, w3, w4p;
            asm("mov.b64 %0, {%1,%2};" : "=l"(w0) : "f"(wr[0]), "f"(wr[1]));
            asm("mov.b64 %0, {%1,%2};" : "=l"(w1) : "f"(wr[2]), "f"(wr[3]));
            asm("mov.b64 %0, {%1,%2};" : "=l"(w2) : "f"(wr[4]), "f"(wr[5]));
            asm("mov.b64 %0, {%1,%2};" : "=l"(w3) : "f"(wr[6]), "f"(wr[7]));
            asm("mov.b64 %0, {%1,%2};" : "=l"(w4p) : "f"(wr[8]), "f"(0.0f));
            #pragma unroll
            for (int r = 0; r < 4; r++) {
                float xv = (d == 0) ? xr[r].x : (d == 1) ? xr[r].y
                         : (d == 2) ? xr[r].z : xr[r].w;
                unsigned long long x2;
                asm("mov.b64 %0, {%1,%1};" : "=l"(x2) : "f"(xv));
                asm("fma.rn.f32x2 %0, %1, %2, %0;" : "+l"(acc[r][0]) : "l"(x2), "l"(w0));
                asm("fma.rn.f32x2 %0, %1, %2, %0;" : "+l"(acc[r][1]) : "l"(x2), "l"(w1));
                asm("fma.rn.f32x2 %0, %1, %2, %0;" : "+l"(acc[r][2]) : "l"(x2), "l"(w2));
                asm("fma.rn.f32x2 %0, %1, %2, %0;" : "+l"(acc[r][3]) : "l"(x2), "l"(w3));
                asm("fma.rn.f32x2 %0, %1, %2, %0;" : "+l"(acc[r][4]) : "l"(x2), "l"(w4p));
            }
        }
    }

    #pragma unroll
    for (int r = 0; r < 4; r++) {
        float a[9];
        #pragma unroll
        for (int p = 0; p < 4; p++) {
            float lo, hi;
            asm("mov.b64 {%0,%1}, %2;" : "=f"(lo), "=f"(hi) : "l"(acc[r][p]));
            a[2 * p] = lo; a[2 * p + 1] = hi;
        }
        { float lo, hi;
          asm("mov.b64 {%0,%1}, %2;" : "=f"(lo), "=f"(hi) : "l"(acc[r][4]));
          a[8] = lo; (void)hi; }
        #pragma unroll
        for (int l = 0; l < 9; l++) {
            float v = a[l];
            v += __shfl_xor_sync(0xffffffffu, v, 16);
            v += __shfl_xor_sync(0xffffffffu, v, 8);
            v += __shfl_xor_sync(0xffffffffu, v, 4);
            v += __shfl_xor_sync(0xffffffffu, v, 2);
            v += __shfl_xor_sync(0xffffffffu, v, 1);
            a[l] = v;
        }
        if (lane < LL)
            g_logits[(size_t)(row0 + r) * LL + lane] = a[lane] + bs[lane];
    }
}

// ---------------------------------------------------------------------------
// Kernel 2: per-batch CRF.
//  warp 0   : exact serial Viterbi chain (alphas -> smem)
//  warps 1-3: chunk-parallel logZ (matrix composition), then combine + score
//  all      : bp recompute, map-scan backtrace, fused metrics, ticket write.
// ---------------------------------------------------------------------------
__global__ void __launch_bounds__(128) crf_kernel(const float* __restrict__ trans,
                                                  const int* __restrict__ label,
                                                  const int* __restrict__ seqlen,
                                                  float* __restrict__ outF) {
    extern __shared__ __align__(16) char smem_raw[];
    CrfSmem* S = (CrfSmem*)smem_raw;

    int b = blockIdx.x;
    int tid = threadIdx.x, lane = tid & 31, warp = tid >> 5;
    int sl = seqlen[b];

    // ---- stage: logits -> slog, swexp = 2^(logit*log2e); T, P=exp(T) ----
    {
        const float4* src = (const float4*)(g_logits + (size_t)b * TT * LL);
        float4* dst = (float4*)S->slog;
        float4* dwe = (float4*)S->swexp;
        for (int i = tid; i < TT * LL / 4; i += 128) {
            float4 v = src[i];
            dst[i] = v;
            float4 e;
            e.x = ex2f_(v.x * LOG2E); e.y = ex2f_(v.y * LOG2E);
            e.z = ex2f_(v.z * LOG2E); e.w = ex2f_(v.w * LOG2E);
            dwe[i] = e;
        }
        if (tid < LL * LL) {
            float t = trans[tid];
            S->Ts[tid] = t;
            S->sP[tid] = ex2f_(t * LOG2E);
        }
    }
    __syncthreads();

    int j = (lane < LL) ? lane : (LL - 1);

    if (warp == 0) {
        // ================= exact serial Viterbi =================
        float Tj[9];
        #pragma unroll
        for (int i = 0; i < 9; i++) Tj[i] = S->Ts[i * LL + j];
        float a = S->slog[j];
        if (lane < LL) S->astore[j] = a;
        float lgc = S->slog[LL + j];                  // logit for t=1

        for (int t = 1; t < sl; t++) {
            float av[9];
            #pragma unroll
            for (int i = 0; i < 9; i++) av[i] = __shfl_sync(0xffffffffu, a, i);
            int tnx = (t + 1 < TT) ? (t + 1) : (TT - 1);
            float lgn = S->slog[tnx * LL + j];        // prefetch next logit
            float v0 = av[0] + Tj[0], v1 = av[1] + Tj[1], v2 = av[2] + Tj[2],
                  v3 = av[3] + Tj[3], v4 = av[4] + Tj[4], v5 = av[5] + Tj[5],
                  v6 = av[6] + Tj[6], v7 = av[7] + Tj[7], v8 = av[8] + Tj[8];
            float best = fmaxf(fmaxf(fmaxf(v0, v1), fmaxf(v2, v3)),
                               fmaxf(fmaxf(fmaxf(v4, v5), fmaxf(v6, v7)), v8));
            a = best + lgc;
            lgc = lgn;
            if (lane < LL) S->astore[t * LL + lane] = a;
        }
        float av[9];
        #pragma unroll
        for (int i = 0; i < 9; i++) av[i] = __shfl_sync(0xffffffffu, a, i);
        float best = av[0];
        int last = 0;
        #pragma unroll
        for (int i = 1; i < 9; i++)
            if (av[i] > best) { best = av[i]; last = i; }
        if (lane == 0) S->s_lasti = last;
    } else {
        // ================= chunk-parallel logZ =================
        int wl = tid - 32;                 // 0..95
        int g = wl / 9, cj = wl - 9 * g;   // group, column
        int NS = sl - 1;
        int Cs = (NS + NG - 1) / NG;       // chunk size (0 if sl==1)
        int t0 = 1 + g * Cs;
        int t1 = min(t0 + Cs, sl);

        if (wl < 90) {
            float P[81];
            #pragma unroll
            for (int k = 0; k < 81; k++) P[k] = S->sP[k];

            float v[9];
            int E = 0;
            if (Cs > 0 && t0 < t1) {
                // first step: column j of D_{t0} P^T
                const float* w = S->swexp + t0 * LL;
                #pragma unroll
                for (int m = 0; m < 9; m++) v[m] = w[m] * P[cj * 9 + m];
                // subsequent steps
                for (int t = t0 + 1; t < t1; t++) {
                    const float* wt = S->swexp + t * LL;
                    float nv[9];
                    #pragma unroll
                    for (int m = 0; m < 9; m++) {
                        float s = v[0] * P[m];
                        #pragma unroll
                        for (int i = 1; i < 9; i++) s = fmaf(v[i], P[i * 9 + m], s);
                        nv[m] = s * wt[m];
                    }
                    unsigned bits = __float_as_uint(nv[0]);
                    int e = (int)(bits >> 23) - 127;
                    E += e;
                    float factor = __uint_as_float((unsigned)(127 - e) << 23);
                    #pragma unroll
                    for (int m = 0; m < 9; m++) v[m] = nv[m] * factor;
                }
            } else {
                #pragma unroll
                for (int m = 0; m < 9; m++) v[m] = (m == cj) ? 1.0f : 0.0f;
                E = 0;
            }
            S->sE[g][cj] = E;
            // store column after group-normalization (below, after barrier)
            // stash v temporarily in sM
            #pragma unroll
            for (int m = 0; m < 9; m++) S->sM[g][m][cj] = v[m];
        }
        asm volatile("bar.sync 1, 96;" ::: "memory");
        if (wl < 90) {
            int Emax = S->sE[g][0];
            #pragma unroll
            for (int i = 1; i < 9; i++) Emax = max(Emax, S->sE[g][i]);
            int E = S->sE[g][cj];
            int d = E - Emax;                    // <= 0
            float adj = (d < -120) ? 0.0f : __uint_as_float((unsigned)(127 + d) << 23);
            #pragma unroll
            for (int m = 0; m < 9; m++) S->sM[g][m][cj] *= adj;
            if (cj == 0) S->sEg[g] = Emax;
        }
        asm volatile("bar.sync 1, 96;" ::: "memory");

        if (warp == 1) {
            // ---- sequential combine over NG chunks (lanes 0-8 active) ----
            float p0 = S->slog[0] * LOG2E;
            float alpha = ex2f_(S->slog[j] * LOG2E - p0);
            int A = 0;
            for (int g2 = 0; g2 < NG; g2++) {
                float av2[9];
                #pragma unroll
                for (int i = 0; i < 9; i++) av2[i] = __shfl_sync(0xffffffffu, alpha, i);
                float s = S->sM[g2][j][0] * av2[0];
                #pragma unroll
                for (int i2 = 1; i2 < 9; i2++)
                    s = fmaf(S->sM[g2][j][i2], av2[i2], s);
                float s0 = __shfl_sync(0xffffffffu, s, 0);
                unsigned bits = __float_as_uint(s0);
                int e = (int)(bits >> 23) - 127;
                A += e + S->sEg[g2];
                float factor = __uint_as_float((unsigned)(127 - e) << 23);
                alpha = s * factor;
            }
            float cv[9];
            #pragma unroll
            for (int i = 0; i < 9; i++) cv[i] = __shfl_sync(0xffffffffu, alpha, i);
            float sum = ((cv[0] + cv[1]) + (cv[2] + cv[3]))
                      + (((cv[4] + cv[5]) + (cv[6] + cv[7])) + cv[8]);
            float logZ = (lg2f_(sum) + (float)A + p0) * LN2;
            if (lane == 0) S->s_logZ = logZ;
            __syncwarp();

            // ---- gold-path score (full warp 1) ----
            const int* lab = label + b * TT;
            float sc = 0.0f;
            for (int t = lane; t < sl; t += 32) {
                int lt = lab[t];
                sc += S->slog[t * LL + lt];
                if (t > 0) sc += S->Ts[lab[t - 1] * LL + lt];
            }
            sc = wredf(sc);
            if (lane == 0) g_ll[b] = S->s_logZ - sc;
        }
    }
    __syncthreads();

    // ---- parallel backpointer recompute ----
    if (tid < 126) {
        int jj = tid % 9, g = tid / 9;    // 14 groups
        float Tc[9];
        #pragma unroll
        for (int i = 0; i < 9; i++) Tc[i] = S->Ts[i * LL + jj];
        for (int t = 1 + g; t < sl; t += 14) {
            const float* ap = S->astore + (t - 1) * LL;
            float bv = ap[0] + Tc[0];
            int bi = 0;
            #pragma unroll
            for (int i = 1; i < 9; i++) {
                float v = ap[i] + Tc[i];
                if (v > bv) { bv = v; bi = i; }
            }
            S->sbp[t * LL + jj] = (unsigned char)bi;
        }
    }
    __syncthreads();

    int last = S->s_lasti;
    for (int t = sl - 1 + tid; t < TT; t += 128) S->stag[t] = (unsigned char)last;

    // ---- parallel backtrace via map suffix-scan (warp 0) ----
    if (warp == 0 && sl > 1) {
        int N = sl - 1;
        int C = (N + 31) >> 5;
        int a0 = 1 + lane * C;
        int b0 = min(a0 + C, sl);
        unsigned long long Pm = MAP_IDENTITY;
        for (int m = a0; m < b0; m++) {
            const unsigned char* row = S->sbp + m * LL;
            unsigned long long f = 0;
            #pragma unroll
            for (int i = 0; i < 9; i++)
                f |= (unsigned long long)row[i] << (4 * i);
            Pm = map_compose(Pm, f);
        }
        #pragma unroll
        for (int off = 1; off < 32; off <<= 1) {
            unsigned long long q = __shfl_down_sync(0xffffffffu, Pm, off);
            if (lane + off < 32) Pm = map_compose(Pm, q);
        }
        unsigned long long R = __shfl_down_sync(0xffffffffu, Pm, 1);
        if (lane == 31) R = MAP_IDENTITY;
        if (a0 < sl) {
            int xcur = (int)((R >> (4 * last)) & 15ull);
            for (int m = b0 - 1; m >= a0; m--) {
                xcur = S->sbp[m * LL + xcur];
                S->stag[m - 1] = (unsigned char)xcur;
            }
        }
    }
    __syncthreads();

    // ---- vit output + fused metrics ----
    float* vout = outF + b * TT;
    const int* lab = label + b * TT;
    int tp = 0, tn = 0, fp = 0, corr = 0;
    for (int i = tid; i < TT; i += 128) {
        int vi = S->stag[i];
        vout[i] = (float)vi;
        int la = lab[i];
        if (la > 0) { if (vi == la) tp++; else tn++; }   // unmasked, per reference
        if (i < sl) {
            if (vi == la) corr++;
            if (la == 0 && vi > 0) fp++;
        }
    }
    tp = wredi(tp); tn = wredi(tn); fp = wredi(fp); corr = wredi(corr);
    if (lane == 0) {
        atomicAdd(&g_red[0], (float)tp);
        atomicAdd(&g_red[1], (float)tn);
        atomicAdd(&g_red[2], (float)fp);
        atomicAdd(&g_red[3], (float)corr);
    }

    // ---- completion ticket; last block writes scalars ----
    __threadfence();
    __syncthreads();
    if (tid == 0) {
        int old = atomicAdd(&g_tick, 1);
        S->s_isLast = (old == BB - 1);
    }
    __syncthreads();
    if (S->s_isLast && warp == 0) {
        __threadfence();
        float lsum = g_ll[lane] + g_ll[lane + 32];
        int sls = seqlen[lane] + seqlen[lane + 32];
        lsum = wredf(lsum);
        sls = wredi(sls);
        if (lane == 0) {
            outF[BB * TT + 0] = g_red[0];                 // tp
            outF[BB * TT + 1] = g_red[1];                 // tn
            outF[BB * TT + 2] = g_red[2];                 // fp
            outF[BB * TT + 3] = lsum / (float)BB;         // loss
            outF[BB * TT + 4] = g_red[3] / (float)sls;    // accuracy
            g_tick = 0;                                   // reset for replay
        }
    }
}

// ---------------------------------------------------------------------------
extern "C" void kernel_launch(void* const* d_in, const int* in_sizes, int n_in,
                              void* d_out, int out_size) {
    const float* x      = (const float*)d_in[0];
    const float* W      = (const float*)d_in[1];
    const float* bias   = (const float*)d_in[2];
    const float* trans  = (const float*)d_in[3];
    const int*   label  = (const int*)d_in[4];
    const int*   seqlen = (const int*)d_in[5];
    float* out = (float*)d_out;

    static int smem_set = 0;
    if (!smem_set) {
        cudaFuncSetAttribute(crf_kernel,
                             cudaFuncAttributeMaxDynamicSharedMemorySize,
                             (int)sizeof(CrfSmem));
        smem_set = 1;
    }

    gemm_kernel<<<1024, 256>>>(x, W, bias);
    crf_kernel<<<BB, 128, sizeof(CrfSmem)>>>(trans, label, seqlen, out);
}